// round 1
// baseline (speedup 1.0000x reference)
#include <cuda_runtime.h>
#include <math.h>

#define NN   6000
#define EE   192000
#define DIN  512
#define HH   128
#define NPB  16          // nodes per block in p-kernel
#define EOSF 1e-10f

// Scratch (static device allocations are allowed; heap allocs are not).
__device__ int   g_win[(size_t)NN * NN];   // winner edge-index+1 per cell (only edge cells touched)
__device__ float g_p[NN];
__device__ float g_dlp[NN];
__device__ float g_dhp[NN];
__device__ float g_ilp[NN];
__device__ float g_ihp[NN];

// Clear winner at all edge cells; init degrees to 1.0 (the +eye term in row sums).
__global__ void k_clear(const int* __restrict__ edges) {
    int t = blockIdx.x * blockDim.x + threadIdx.x;
    if (t < EE) {
        int u = edges[t], v = edges[EE + t];
        g_win[u * NN + v] = 0;
    }
    if (t < NN) { g_dlp[t] = 1.0f; g_dhp[t] = 1.0f; }
}

// Last-edge-wins dedup: winner = max edge index + 1.
__global__ void k_max(const int* __restrict__ edges) {
    int e = blockIdx.x * blockDim.x + threadIdx.x;
    if (e >= EE) return;
    int u = edges[e], v = edges[EE + e];
    atomicMax(&g_win[u * NN + v], e + 1);
}

// p[n] = sum_h relu(feat[n]·w_emb[:,h] + b_emb[h]) * (w_mlp[h] + w_mlp[H+h])
// 16 nodes per block, thread = h. Features cached in smem; w_emb (256KB) streams
// from L2, coalesced across h, reused 16x per block.
__global__ void __launch_bounds__(HH) k_p(const float* __restrict__ feat,
                                          const float* __restrict__ wemb,
                                          const float* __restrict__ bemb,
                                          const float* __restrict__ wmlp) {
    __shared__ float sf[NPB][DIN];
    int h  = threadIdx.x;
    int n0 = blockIdx.x * NPB;

    // cooperative vectorized load of 16 feature rows
    const float4* f4 = (const float4*)(feat + (size_t)n0 * DIN);
    float4* s4 = (float4*)&sf[0][0];
    const int total4 = NPB * DIN / 4;  // 2048
    for (int i = h; i < total4; i += HH) s4[i] = f4[i];
    __syncthreads();

    float acc[NPB];
#pragma unroll
    for (int j = 0; j < NPB; j++) acc[j] = 0.0f;

    for (int d = 0; d < DIN; d += 4) {
        float w0 = wemb[(d + 0) * HH + h];
        float w1 = wemb[(d + 1) * HH + h];
        float w2 = wemb[(d + 2) * HH + h];
        float w3 = wemb[(d + 3) * HH + h];
#pragma unroll
        for (int j = 0; j < NPB; j++) {
            float4 f = *(const float4*)&sf[j][d];
            acc[j] = fmaf(f.x, w0, acc[j]);
            acc[j] = fmaf(f.y, w1, acc[j]);
            acc[j] = fmaf(f.z, w2, acc[j]);
            acc[j] = fmaf(f.w, w3, acc[j]);
        }
    }

    float b  = bemb[h];
    float ws = wmlp[h] + wmlp[HH + h];
    __shared__ float red[4][NPB];
#pragma unroll
    for (int j = 0; j < NPB; j++) {
        float v = acc[j] + b;
        v = (v > 0.0f) ? v * ws : 0.0f;
#pragma unroll
        for (int off = 16; off; off >>= 1) v += __shfl_down_sync(0xffffffffu, v, off);
        if ((h & 31) == 0) red[h >> 5][j] = v;
    }
    __syncthreads();
    if (h < NPB)
        g_p[n0 + h] = red[0][h] + red[1][h] + red[2][h] + red[3][h];
}

// Per-edge gating weights + winner-only degree accumulation (row sums).
__global__ void k_edge(const int* __restrict__ edges, const float* __restrict__ gn,
                       const float* __restrict__ bmlp,
                       float* __restrict__ wlp_out, float* __restrict__ whp_out) {
    int e = blockIdx.x * blockDim.x + threadIdx.x;
    if (e >= EE) return;
    int u = edges[e], v = edges[EE + e];
    float raw = 0.5f * (g_p[u] + g_p[v]) + bmlp[0];
    float x   = gn[e] + raw;               // TEMP = 1
    float wlp = 1.0f / (1.0f + expf(-x));
    wlp_out[e] = wlp;
    whp_out[e] = 1.0f - wlp;
    if (g_win[u * NN + v] == e + 1) {       // deduped adjacency contribution
        atomicAdd(&g_dlp[u], wlp);
        atomicAdd(&g_dhp[u], 1.0f - wlp);
    }
}

__global__ void k_inv() {
    int i = blockIdx.x * blockDim.x + threadIdx.x;
    if (i >= NN) return;
    g_ilp[i] = 1.0f / (sqrtf(g_dlp[i]) + EOSF);
    g_ihp[i] = 1.0f / (sqrtf(g_dhp[i]) + EOSF);
}

// Diagonals: adj_lp gets the eye contribution (1*inv_i^2); adj_hp starts as identity.
__global__ void k_diag(float* __restrict__ adj_lp, float* __restrict__ adj_hp) {
    int i = blockIdx.x * blockDim.x + threadIdx.x;
    if (i >= NN) return;
    size_t c = (size_t)i * NN + i;
    float il = g_ilp[i];
    adj_lp[c] = il * il;
    adj_hp[c] = 1.0f;
}

// Scatter edge cells into the three dense matrices.
__global__ void k_scatter(const int* __restrict__ edges, const float* __restrict__ wlp_out,
                          float* __restrict__ adj_lp, float* __restrict__ adj_hp,
                          float* __restrict__ unnorm) {
    int e = blockIdx.x * blockDim.x + threadIdx.x;
    if (e >= EE) return;
    int u = edges[e], v = edges[EE + e];
    int cell = u * NN + v;
    unnorm[cell] = 1.0f;                    // mask / adj_unnorm (duplicates write same value)
    if (g_win[cell] == e + 1) {
        float wlp = wlp_out[e];
        adj_lp[cell] += wlp * g_ilp[u] * g_ilp[v];          // += handles self-edge diag
        float extra = (u == v) ? 1.0f : 0.0f;               // eye term inside normalized hp at self-edges
        adj_hp[cell] -= ((1.0f - wlp) + extra) * g_ihp[u] * g_ihp[v];
    }
}

extern "C" void kernel_launch(void* const* d_in, const int* in_sizes, int n_in,
                              void* d_out, int out_size) {
    const float* feat  = (const float*)d_in[0];
    const int*   edges = (const int*)  d_in[1];
    const float* wemb  = (const float*)d_in[2];
    const float* bemb  = (const float*)d_in[3];
    const float* wmlp  = (const float*)d_in[4];
    const float* bmlp  = (const float*)d_in[5];
    const float* gn    = (const float*)d_in[6];

    float* out     = (float*)d_out;
    float* adj_lp  = out;
    float* adj_hp  = out + (size_t)NN * NN;
    float* wlp     = out + 2ull * NN * NN;
    float* whp     = wlp + EE;
    float* unnorm  = whp + EE;

    // Zero-fill the dense matrices (memset nodes are graph-capturable).
    cudaMemsetAsync(adj_lp, 0, 2ull * NN * NN * sizeof(float), 0);
    cudaMemsetAsync(unnorm, 0, (size_t)NN * NN * sizeof(float), 0);

    const int TB = 256;
    k_clear  <<<(EE + TB - 1) / TB, TB>>>(edges);
    k_max    <<<(EE + TB - 1) / TB, TB>>>(edges);
    k_p      <<<NN / NPB, HH>>>(feat, wemb, bemb, wmlp);
    k_edge   <<<(EE + TB - 1) / TB, TB>>>(edges, gn, bmlp, wlp, whp);
    k_inv    <<<(NN + TB - 1) / TB, TB>>>();
    k_diag   <<<(NN + TB - 1) / TB, TB>>>(adj_lp, adj_hp);
    k_scatter<<<(EE + TB - 1) / TB, TB>>>(edges, wlp, adj_lp, adj_hp, unnorm);
}

// round 2
// speedup vs baseline: 1.0239x; 1.0239x over previous
#include <cuda_runtime.h>
#include <math.h>

#define NN   6000
#define EE   192000
#define DIN  512
#define HH   128
#define NPB  8           // nodes per block in p-kernel
#define EOSF 1e-10f

// Scratch (__device__ globals allowed; heap allocs are not).
__device__ int   g_win[(size_t)NN * NN];   // winner edge-index+1 per cell (only edge cells touched)
__device__ float g_p[NN];
__device__ float g_dlp[NN];
__device__ float g_dhp[NN];
__device__ float g_ilp[NN];
__device__ float g_ihp[NN];

// Clear winner at all edge cells; init degrees to 1.0 (the +eye term in row sums).
__global__ void k_clear(const int* __restrict__ edges) {
    int t = blockIdx.x * blockDim.x + threadIdx.x;
    if (t < EE) {
        int u = edges[t], v = edges[EE + t];
        g_win[u * NN + v] = 0;
    }
    if (t < NN) { g_dlp[t] = 1.0f; g_dhp[t] = 1.0f; }
}

// Last-edge-wins dedup: winner = max edge index + 1.
__global__ void k_max(const int* __restrict__ edges) {
    int e = blockIdx.x * blockDim.x + threadIdx.x;
    if (e >= EE) return;
    int u = edges[e], v = edges[EE + e];
    atomicMax(&g_win[u * NN + v], e + 1);
}

// p[n] = sum_h relu(feat[n]·w_emb[:,h] + b_emb[h]) * (w_mlp[h] + w_mlp[H+h])
__global__ void __launch_bounds__(HH) k_p(const float* __restrict__ feat,
                                          const float* __restrict__ wemb,
                                          const float* __restrict__ bemb,
                                          const float* __restrict__ wmlp) {
    __shared__ float sf[NPB][DIN];
    int h  = threadIdx.x;
    int n0 = blockIdx.x * NPB;

    const float4* f4 = (const float4*)(feat + (size_t)n0 * DIN);
    float4* s4 = (float4*)&sf[0][0];
    const int total4 = NPB * DIN / 4;
    for (int i = h; i < total4; i += HH) s4[i] = f4[i];
    __syncthreads();

    float acc[NPB];
#pragma unroll
    for (int j = 0; j < NPB; j++) acc[j] = 0.0f;

    for (int d = 0; d < DIN; d += 4) {
        float w0 = wemb[(d + 0) * HH + h];
        float w1 = wemb[(d + 1) * HH + h];
        float w2 = wemb[(d + 2) * HH + h];
        float w3 = wemb[(d + 3) * HH + h];
#pragma unroll
        for (int j = 0; j < NPB; j++) {
            float4 f = *(const float4*)&sf[j][d];
            acc[j] = fmaf(f.x, w0, acc[j]);
            acc[j] = fmaf(f.y, w1, acc[j]);
            acc[j] = fmaf(f.z, w2, acc[j]);
            acc[j] = fmaf(f.w, w3, acc[j]);
        }
    }

    float b  = bemb[h];
    float ws = wmlp[h] + wmlp[HH + h];
    __shared__ float red[4][NPB];
#pragma unroll
    for (int j = 0; j < NPB; j++) {
        float v = acc[j] + b;
        v = (v > 0.0f) ? v * ws : 0.0f;
#pragma unroll
        for (int off = 16; off; off >>= 1) v += __shfl_down_sync(0xffffffffu, v, off);
        if ((h & 31) == 0) red[h >> 5][j] = v;
    }
    __syncthreads();
    if (h < NPB)
        g_p[n0 + h] = red[0][h] + red[1][h] + red[2][h] + red[3][h];
}

// Per-edge gating weights + winner-only degree accumulation (row sums).
__global__ void k_edge(const int* __restrict__ edges, const float* __restrict__ gn,
                       const float* __restrict__ bmlp,
                       float* __restrict__ wlp_out, float* __restrict__ whp_out) {
    int e = blockIdx.x * blockDim.x + threadIdx.x;
    if (e >= EE) return;
    int u = edges[e], v = edges[EE + e];
    float raw = 0.5f * (g_p[u] + g_p[v]) + bmlp[0];
    float x   = gn[e] + raw;               // TEMP = 1
    float wlp = 1.0f / (1.0f + expf(-x));
    wlp_out[e] = wlp;
    whp_out[e] = 1.0f - wlp;
    if (g_win[u * NN + v] == e + 1) {       // deduped adjacency contribution
        atomicAdd(&g_dlp[u], wlp);
        atomicAdd(&g_dhp[u], 1.0f - wlp);
    }
}

__global__ void k_inv() {
    int i = blockIdx.x * blockDim.x + threadIdx.x;
    if (i >= NN) return;
    g_ilp[i] = 1.0f / (sqrtf(g_dlp[i]) + EOSF);
    g_ihp[i] = 1.0f / (sqrtf(g_dhp[i]) + EOSF);
}

// Fused scatter + diagonal. Pure stores, no read-modify-write:
//  - edge cells (winner): closed-form value incl. self-edge diagonal case
//  - diagonal cells with no self-edge: base values
__global__ void k_finish(const int* __restrict__ edges, const float* __restrict__ wlp_out,
                         float* __restrict__ adj_lp, float* __restrict__ adj_hp,
                         float* __restrict__ unnorm) {
    int t = blockIdx.x * blockDim.x + threadIdx.x;
    if (t < EE) {
        int u = edges[t], v = edges[EE + t];
        size_t cell = (size_t)u * NN + v;
        unnorm[cell] = 1.0f;
        if (g_win[cell] == t + 1) {
            float wlp = wlp_out[t];
            float il = g_ilp[u] * g_ilp[v];
            float ih = g_ihp[u] * g_ihp[v];
            if (u == v) {
                adj_lp[cell] = (1.0f + wlp) * il;            // eye + self-edge, normalized
                adj_hp[cell] = 1.0f - (2.0f - wlp) * ih;     // 1 - (whp + 1)*ih
            } else {
                adj_lp[cell] = wlp * il;
                adj_hp[cell] = -(1.0f - wlp) * ih;
            }
        }
    } else if (t < EE + NN) {
        int i = t - EE;
        size_t cell = (size_t)i * NN + i;
        if (g_win[cell] == 0) {              // no self-edge at (i,i) this call
            float il = g_ilp[i];
            adj_lp[cell] = il * il;
            adj_hp[cell] = 1.0f;
        }
    }
}

extern "C" void kernel_launch(void* const* d_in, const int* in_sizes, int n_in,
                              void* d_out, int out_size) {
    const float* feat  = (const float*)d_in[0];
    const int*   edges = (const int*)  d_in[1];
    const float* wemb  = (const float*)d_in[2];
    const float* bemb  = (const float*)d_in[3];
    const float* wmlp  = (const float*)d_in[4];
    const float* bmlp  = (const float*)d_in[5];
    const float* gn    = (const float*)d_in[6];

    float* out     = (float*)d_out;
    float* adj_lp  = out;
    float* adj_hp  = out + (size_t)NN * NN;
    float* wlp     = out + 2ull * NN * NN;
    float* whp     = wlp + EE;
    float* unnorm  = whp + EE;

    // Lazy one-time handle creation (identical work every call; handles only).
    static cudaStream_t s_fill = nullptr, s_p = nullptr;
    static cudaEvent_t ev_fork = nullptr, ev_fill = nullptr, ev_p = nullptr;
    if (!s_fill) {
        cudaStreamCreateWithFlags(&s_fill, cudaStreamNonBlocking);
        cudaStreamCreateWithFlags(&s_p,    cudaStreamNonBlocking);
        cudaEventCreateWithFlags(&ev_fork, cudaEventDisableTiming);
        cudaEventCreateWithFlags(&ev_fill, cudaEventDisableTiming);
        cudaEventCreateWithFlags(&ev_p,    cudaEventDisableTiming);
    }

    const int TB = 256;

    // Fork: fills and k_p run concurrently with the clear/max chain.
    cudaEventRecord(ev_fork, 0);
    cudaStreamWaitEvent(s_fill, ev_fork, 0);
    cudaStreamWaitEvent(s_p,    ev_fork, 0);

    // Side stream 1: 432 MB of zero-fill (the HBM-store floor of this problem).
    cudaMemsetAsync(adj_lp, 0, 2ull * NN * NN * sizeof(float), s_fill);
    cudaMemsetAsync(unnorm, 0, (size_t)NN * NN * sizeof(float), s_fill);
    cudaEventRecord(ev_fill, s_fill);

    // Side stream 2: node scalar projection (independent of winner bookkeeping).
    k_p<<<NN / NPB, HH, 0, s_p>>>(feat, wemb, bemb, wmlp);
    cudaEventRecord(ev_p, s_p);

    // Main chain: winner bookkeeping.
    k_clear<<<(EE + TB - 1) / TB, TB>>>(edges);
    k_max  <<<(EE + TB - 1) / TB, TB>>>(edges);

    // Join k_p, then edge gating + degrees + inverse norms.
    cudaStreamWaitEvent(0, ev_p, 0);
    k_edge<<<(EE + TB - 1) / TB, TB>>>(edges, gn, bmlp, wlp, whp);
    k_inv <<<(NN + TB - 1) / TB, TB>>>();

    // Join fills, then the single store-only finish pass (edges + diagonal).
    cudaStreamWaitEvent(0, ev_fill, 0);
    k_finish<<<(EE + NN + TB - 1) / TB, TB>>>(edges, wlp, adj_lp, adj_hp, unnorm);
}

// round 3
// speedup vs baseline: 1.0361x; 1.0120x over previous
#include <cuda_runtime.h>
#include <math.h>

#define NN   6000
#define EE   192000
#define DIN  512
#define HH   128
#define NPB  8           // nodes per block in p-kernel
#define EOSF 1e-10f

// Scratch (__device__ globals allowed; heap allocs are not).
__device__ int   g_win[(size_t)NN * NN];   // winner edge-index+1 per cell (only edge cells touched)
__device__ float g_p[NN];
__device__ float g_dlp[NN];
__device__ float g_dhp[NN];
__device__ float g_ilp[NN];
__device__ float g_ihp[NN];

// Full-rate zero fill: grid-stride float4 stores (replaces slow memset graph nodes).
__global__ void __launch_bounds__(512) k_fill(float4* __restrict__ dst, size_t n4) {
    size_t i = (size_t)blockIdx.x * blockDim.x + threadIdx.x;
    size_t stride = (size_t)gridDim.x * blockDim.x;
    const float4 z = make_float4(0.f, 0.f, 0.f, 0.f);
    for (; i < n4; i += stride) dst[i] = z;
}

// Clear winner at all edge cells; init degrees to 1.0 (the +eye term in row sums).
__global__ void k_clear(const int* __restrict__ edges) {
    int t = blockIdx.x * blockDim.x + threadIdx.x;
    if (t < EE) {
        int u = edges[t], v = edges[EE + t];
        g_win[u * NN + v] = 0;
    }
    if (t < NN) { g_dlp[t] = 1.0f; g_dhp[t] = 1.0f; }
}

// Last-edge-wins dedup: winner = max edge index + 1.
__global__ void k_max(const int* __restrict__ edges) {
    int e = blockIdx.x * blockDim.x + threadIdx.x;
    if (e >= EE) return;
    int u = edges[e], v = edges[EE + e];
    atomicMax(&g_win[u * NN + v], e + 1);
}

// p[n] = sum_h relu(feat[n]·w_emb[:,h] + b_emb[h]) * (w_mlp[h] + w_mlp[H+h])
__global__ void __launch_bounds__(HH) k_p(const float* __restrict__ feat,
                                          const float* __restrict__ wemb,
                                          const float* __restrict__ bemb,
                                          const float* __restrict__ wmlp) {
    __shared__ float sf[NPB][DIN];
    int h  = threadIdx.x;
    int n0 = blockIdx.x * NPB;

    const float4* f4 = (const float4*)(feat + (size_t)n0 * DIN);
    float4* s4 = (float4*)&sf[0][0];
    const int total4 = NPB * DIN / 4;
    for (int i = h; i < total4; i += HH) s4[i] = f4[i];
    __syncthreads();

    float acc[NPB];
#pragma unroll
    for (int j = 0; j < NPB; j++) acc[j] = 0.0f;

    for (int d = 0; d < DIN; d += 4) {
        float w0 = wemb[(d + 0) * HH + h];
        float w1 = wemb[(d + 1) * HH + h];
        float w2 = wemb[(d + 2) * HH + h];
        float w3 = wemb[(d + 3) * HH + h];
#pragma unroll
        for (int j = 0; j < NPB; j++) {
            float4 f = *(const float4*)&sf[j][d];
            acc[j] = fmaf(f.x, w0, acc[j]);
            acc[j] = fmaf(f.y, w1, acc[j]);
            acc[j] = fmaf(f.z, w2, acc[j]);
            acc[j] = fmaf(f.w, w3, acc[j]);
        }
    }

    float b  = bemb[h];
    float ws = wmlp[h] + wmlp[HH + h];
    __shared__ float red[4][NPB];
#pragma unroll
    for (int j = 0; j < NPB; j++) {
        float v = acc[j] + b;
        v = (v > 0.0f) ? v * ws : 0.0f;
#pragma unroll
        for (int off = 16; off; off >>= 1) v += __shfl_down_sync(0xffffffffu, v, off);
        if ((h & 31) == 0) red[h >> 5][j] = v;
    }
    __syncthreads();
    if (h < NPB)
        g_p[n0 + h] = red[0][h] + red[1][h] + red[2][h] + red[3][h];
}

// Per-edge gating weights + winner-only degree accumulation (row sums).
__global__ void k_edge(const int* __restrict__ edges, const float* __restrict__ gn,
                       const float* __restrict__ bmlp,
                       float* __restrict__ wlp_out, float* __restrict__ whp_out) {
    int e = blockIdx.x * blockDim.x + threadIdx.x;
    if (e >= EE) return;
    int u = edges[e], v = edges[EE + e];
    float raw = 0.5f * (g_p[u] + g_p[v]) + bmlp[0];
    float x   = gn[e] + raw;               // TEMP = 1
    float wlp = 1.0f / (1.0f + expf(-x));
    wlp_out[e] = wlp;
    whp_out[e] = 1.0f - wlp;
    if (g_win[u * NN + v] == e + 1) {       // deduped adjacency contribution
        atomicAdd(&g_dlp[u], wlp);
        atomicAdd(&g_dhp[u], 1.0f - wlp);
    }
}

__global__ void k_inv() {
    int i = blockIdx.x * blockDim.x + threadIdx.x;
    if (i >= NN) return;
    g_ilp[i] = 1.0f / (sqrtf(g_dlp[i]) + EOSF);
    g_ihp[i] = 1.0f / (sqrtf(g_dhp[i]) + EOSF);
}

// Fused scatter + diagonal. Pure stores, no read-modify-write.
__global__ void k_finish(const int* __restrict__ edges, const float* __restrict__ wlp_out,
                         float* __restrict__ adj_lp, float* __restrict__ adj_hp,
                         float* __restrict__ unnorm) {
    int t = blockIdx.x * blockDim.x + threadIdx.x;
    if (t < EE) {
        int u = edges[t], v = edges[EE + t];
        size_t cell = (size_t)u * NN + v;
        unnorm[cell] = 1.0f;
        if (g_win[cell] == t + 1) {
            float wlp = wlp_out[t];
            float il = g_ilp[u] * g_ilp[v];
            float ih = g_ihp[u] * g_ihp[v];
            if (u == v) {
                adj_lp[cell] = (1.0f + wlp) * il;            // eye + self-edge, normalized
                adj_hp[cell] = 1.0f - (2.0f - wlp) * ih;     // 1 - (whp + 1)*ih
            } else {
                adj_lp[cell] = wlp * il;
                adj_hp[cell] = -(1.0f - wlp) * ih;
            }
        }
    } else if (t < EE + NN) {
        int i = t - EE;
        size_t cell = (size_t)i * NN + i;
        if (g_win[cell] == 0) {              // no self-edge at (i,i)
            float il = g_ilp[i];
            adj_lp[cell] = il * il;
            adj_hp[cell] = 1.0f;
        }
    }
}

extern "C" void kernel_launch(void* const* d_in, const int* in_sizes, int n_in,
                              void* d_out, int out_size) {
    const float* feat  = (const float*)d_in[0];
    const int*   edges = (const int*)  d_in[1];
    const float* wemb  = (const float*)d_in[2];
    const float* bemb  = (const float*)d_in[3];
    const float* wmlp  = (const float*)d_in[4];
    const float* bmlp  = (const float*)d_in[5];
    const float* gn    = (const float*)d_in[6];

    float* out     = (float*)d_out;
    float* adj_lp  = out;
    float* adj_hp  = out + (size_t)NN * NN;
    float* wlp     = out + 2ull * NN * NN;
    float* whp     = wlp + EE;
    float* unnorm  = whp + EE;

    static cudaStream_t s_fill = nullptr, s_p = nullptr;
    static cudaEvent_t ev_fork = nullptr, ev_fill = nullptr, ev_p = nullptr;
    if (!s_fill) {
        cudaStreamCreateWithFlags(&s_fill, cudaStreamNonBlocking);
        cudaStreamCreateWithFlags(&s_p,    cudaStreamNonBlocking);
        cudaEventCreateWithFlags(&ev_fork, cudaEventDisableTiming);
        cudaEventCreateWithFlags(&ev_fill, cudaEventDisableTiming);
        cudaEventCreateWithFlags(&ev_p,    cudaEventDisableTiming);
    }

    const int TB = 256;

    // Fork: fill and k_p run concurrently with the clear/max chain.
    cudaEventRecord(ev_fork, 0);
    cudaStreamWaitEvent(s_fill, ev_fork, 0);
    cudaStreamWaitEvent(s_p,    ev_fork, 0);

    // Side stream 1: SM-side zero-fill of adj_lp+adj_hp (contiguous) and unnorm.
    // (w_lp/w_hp region between them is fully overwritten by k_edge.)
    k_fill<<<148 * 16, 512, 0, s_fill>>>((float4*)adj_lp, (2ull * NN * NN) / 4);
    k_fill<<<148 * 8,  512, 0, s_fill>>>((float4*)unnorm, ((size_t)NN * NN) / 4);
    cudaEventRecord(ev_fill, s_fill);

    // Side stream 2: node scalar projection.
    k_p<<<NN / NPB, HH, 0, s_p>>>(feat, wemb, bemb, wmlp);
    cudaEventRecord(ev_p, s_p);

    // Main chain: winner bookkeeping.
    k_clear<<<(EE + TB - 1) / TB, TB>>>(edges);
    k_max  <<<(EE + TB - 1) / TB, TB>>>(edges);

    // Join k_p, then edge gating + degrees + inverse norms.
    cudaStreamWaitEvent(0, ev_p, 0);
    k_edge<<<(EE + TB - 1) / TB, TB>>>(edges, gn, bmlp, wlp, whp);
    k_inv <<<(NN + TB - 1) / TB, TB>>>();

    // Join fill, then the single store-only finish pass (edges + diagonal).
    cudaStreamWaitEvent(0, ev_fill, 0);
    k_finish<<<(EE + NN + TB - 1) / TB, TB>>>(edges, wlp, adj_lp, adj_hp, unnorm);
}

// round 4
// speedup vs baseline: 1.0586x; 1.0217x over previous
#include <cuda_runtime.h>
#include <math.h>

#define NN   6000
#define EE   192000
#define DIN  512
#define HH   128
#define NPB  8           // nodes per block in p-kernel
#define EOSF 1e-10f

// Scratch (__device__ globals allowed; heap allocs are not).
__device__ int   g_win[(size_t)NN * NN];   // winner edge-index+1 per cell (only edge cells touched)
__device__ float g_p[NN];
__device__ float g_dlp[NN];
__device__ float g_dhp[NN];
__device__ float g_ilp[NN];
__device__ float g_ihp[NN];

// Zero fill with streaming (evict-first) stores: avoid L2 write-allocate cost.
__global__ void __launch_bounds__(512) k_fill(float4* __restrict__ dst, size_t n4) {
    size_t i = (size_t)blockIdx.x * blockDim.x + threadIdx.x;
    size_t stride = (size_t)gridDim.x * blockDim.x;
    const float4 z = make_float4(0.f, 0.f, 0.f, 0.f);
    for (; i < n4; i += stride) __stcs(dst + i, z);
}

// Clear winner at all edge cells; init degrees to 1.0 (the +eye term in row sums).
__global__ void k_clear(const int* __restrict__ edges) {
    int t = blockIdx.x * blockDim.x + threadIdx.x;
    if (t < EE) {
        int u = edges[t], v = edges[EE + t];
        g_win[u * NN + v] = 0;
    }
    if (t < NN) { g_dlp[t] = 1.0f; g_dhp[t] = 1.0f; }
}

// Last-edge-wins dedup: winner = max edge index + 1.
__global__ void k_max(const int* __restrict__ edges) {
    int e = blockIdx.x * blockDim.x + threadIdx.x;
    if (e >= EE) return;
    int u = edges[e], v = edges[EE + e];
    atomicMax(&g_win[u * NN + v], e + 1);
}

// p[n] = sum_h relu(feat[n]·w_emb[:,h] + b_emb[h]) * (w_mlp[h] + w_mlp[H+h])
__global__ void __launch_bounds__(HH) k_p(const float* __restrict__ feat,
                                          const float* __restrict__ wemb,
                                          const float* __restrict__ bemb,
                                          const float* __restrict__ wmlp) {
    __shared__ float sf[NPB][DIN];
    int h  = threadIdx.x;
    int n0 = blockIdx.x * NPB;

    const float4* f4 = (const float4*)(feat + (size_t)n0 * DIN);
    float4* s4 = (float4*)&sf[0][0];
    const int total4 = NPB * DIN / 4;
    for (int i = h; i < total4; i += HH) s4[i] = f4[i];
    __syncthreads();

    float acc[NPB];
#pragma unroll
    for (int j = 0; j < NPB; j++) acc[j] = 0.0f;

    for (int d = 0; d < DIN; d += 4) {
        float w0 = wemb[(d + 0) * HH + h];
        float w1 = wemb[(d + 1) * HH + h];
        float w2 = wemb[(d + 2) * HH + h];
        float w3 = wemb[(d + 3) * HH + h];
#pragma unroll
        for (int j = 0; j < NPB; j++) {
            float4 f = *(const float4*)&sf[j][d];
            acc[j] = fmaf(f.x, w0, acc[j]);
            acc[j] = fmaf(f.y, w1, acc[j]);
            acc[j] = fmaf(f.z, w2, acc[j]);
            acc[j] = fmaf(f.w, w3, acc[j]);
        }
    }

    float b  = bemb[h];
    float ws = wmlp[h] + wmlp[HH + h];
    __shared__ float red[4][NPB];
#pragma unroll
    for (int j = 0; j < NPB; j++) {
        float v = acc[j] + b;
        v = (v > 0.0f) ? v * ws : 0.0f;
#pragma unroll
        for (int off = 16; off; off >>= 1) v += __shfl_down_sync(0xffffffffu, v, off);
        if ((h & 31) == 0) red[h >> 5][j] = v;
    }
    __syncthreads();
    if (h < NPB)
        g_p[n0 + h] = red[0][h] + red[1][h] + red[2][h] + red[3][h];
}

// Per-edge gating weights + winner-only degree accumulation (row sums).
__global__ void k_edge(const int* __restrict__ edges, const float* __restrict__ gn,
                       const float* __restrict__ bmlp,
                       float* __restrict__ wlp_out, float* __restrict__ whp_out) {
    int e = blockIdx.x * blockDim.x + threadIdx.x;
    if (e >= EE) return;
    int u = edges[e], v = edges[EE + e];
    float raw = 0.5f * (g_p[u] + g_p[v]) + bmlp[0];
    float x   = gn[e] + raw;               // TEMP = 1
    float wlp = 1.0f / (1.0f + expf(-x));
    wlp_out[e] = wlp;
    whp_out[e] = 1.0f - wlp;
    if (g_win[u * NN + v] == e + 1) {       // deduped adjacency contribution
        atomicAdd(&g_dlp[u], wlp);
        atomicAdd(&g_dhp[u], 1.0f - wlp);
    }
}

__global__ void k_inv() {
    int i = blockIdx.x * blockDim.x + threadIdx.x;
    if (i >= NN) return;
    g_ilp[i] = 1.0f / (sqrtf(g_dlp[i]) + EOSF);
    g_ihp[i] = 1.0f / (sqrtf(g_dhp[i]) + EOSF);
}

// Unnorm/mask scatter: depends only on its fill + edges. Duplicates write same value.
__global__ void k_fin_unnorm(const int* __restrict__ edges, float* __restrict__ unnorm) {
    int t = blockIdx.x * blockDim.x + threadIdx.x;
    if (t >= EE) return;
    int u = edges[t], v = edges[EE + t];
    __stcs(&unnorm[(size_t)u * NN + v], 1.0f);
}

// Adjacency scatter + diagonal. Pure stores, no RMW (self-edge case closed-form).
__global__ void k_fin_adj(const int* __restrict__ edges, const float* __restrict__ wlp_out,
                          float* __restrict__ adj_lp, float* __restrict__ adj_hp) {
    int t = blockIdx.x * blockDim.x + threadIdx.x;
    if (t < EE) {
        int u = edges[t], v = edges[EE + t];
        size_t cell = (size_t)u * NN + v;
        if (g_win[cell] == t + 1) {
            float wlp = wlp_out[t];
            float il = g_ilp[u] * g_ilp[v];
            float ih = g_ihp[u] * g_ihp[v];
            if (u == v) {
                __stcs(&adj_lp[cell], (1.0f + wlp) * il);          // eye + self-edge, normalized
                __stcs(&adj_hp[cell], 1.0f - (2.0f - wlp) * ih);   // 1 - (whp + 1)*ih
            } else {
                __stcs(&adj_lp[cell], wlp * il);
                __stcs(&adj_hp[cell], -(1.0f - wlp) * ih);
            }
        }
    } else if (t < EE + NN) {
        int i = t - EE;
        size_t cell = (size_t)i * NN + i;
        if (g_win[cell] == 0) {              // no self-edge at (i,i)
            float il = g_ilp[i];
            __stcs(&adj_lp[cell], il * il);
            __stcs(&adj_hp[cell], 1.0f);
        }
    }
}

extern "C" void kernel_launch(void* const* d_in, const int* in_sizes, int n_in,
                              void* d_out, int out_size) {
    const float* feat  = (const float*)d_in[0];
    const int*   edges = (const int*)  d_in[1];
    const float* wemb  = (const float*)d_in[2];
    const float* bemb  = (const float*)d_in[3];
    const float* wmlp  = (const float*)d_in[4];
    const float* bmlp  = (const float*)d_in[5];
    const float* gn    = (const float*)d_in[6];

    float* out     = (float*)d_out;
    float* adj_lp  = out;
    float* adj_hp  = out + (size_t)NN * NN;
    float* wlp     = out + 2ull * NN * NN;
    float* whp     = wlp + EE;
    float* unnorm  = whp + EE;

    static cudaStream_t s_fill = nullptr, s_p = nullptr;
    static cudaEvent_t ev_fork = nullptr, ev_fu = nullptr, ev_fa = nullptr, ev_p = nullptr;
    if (!s_fill) {
        cudaStreamCreateWithFlags(&s_fill, cudaStreamNonBlocking);
        cudaStreamCreateWithFlags(&s_p,    cudaStreamNonBlocking);
        cudaEventCreateWithFlags(&ev_fork, cudaEventDisableTiming);
        cudaEventCreateWithFlags(&ev_fu,   cudaEventDisableTiming);
        cudaEventCreateWithFlags(&ev_fa,   cudaEventDisableTiming);
        cudaEventCreateWithFlags(&ev_p,    cudaEventDisableTiming);
    }

    const int TB = 256;

    // Fork.
    cudaEventRecord(ev_fork, 0);
    cudaStreamWaitEvent(s_fill, ev_fork, 0);
    cudaStreamWaitEvent(s_p,    ev_fork, 0);

    // Side stream 1: streaming-store zero fills. Unnorm region first (its scatter
    // has no other dependencies), then the two adjacency matrices (contiguous).
    k_fill<<<148 * 8,  512, 0, s_fill>>>((float4*)unnorm, ((size_t)NN * NN) / 4);
    cudaEventRecord(ev_fu, s_fill);
    k_fill<<<148 * 16, 512, 0, s_fill>>>((float4*)adj_lp, (2ull * NN * NN) / 4);
    cudaEventRecord(ev_fa, s_fill);

    // Side stream 2: node scalar projection, then unnorm scatter once its fill lands.
    k_p<<<NN / NPB, HH, 0, s_p>>>(feat, wemb, bemb, wmlp);
    cudaEventRecord(ev_p, s_p);
    cudaStreamWaitEvent(s_p, ev_fu, 0);
    k_fin_unnorm<<<(EE + TB - 1) / TB, TB, 0, s_p>>>(edges, unnorm);

    // Main chain: winner bookkeeping, gating, norms (all overlap the adj fill).
    k_clear<<<(EE + TB - 1) / TB, TB>>>(edges);
    k_max  <<<(EE + TB - 1) / TB, TB>>>(edges);
    cudaStreamWaitEvent(0, ev_p, 0);
    k_edge<<<(EE + TB - 1) / TB, TB>>>(edges, gn, bmlp, wlp, whp);
    k_inv <<<(NN + TB - 1) / TB, TB>>>();

    // Join adj fill, then the adjacency scatter tail.
    cudaStreamWaitEvent(0, ev_fa, 0);
    k_fin_adj<<<(EE + NN + TB - 1) / TB, TB>>>(edges, wlp, adj_lp, adj_hp);

    // Join the unnorm branch so the graph has a single terminal.
    static cudaEvent_t ev_un = nullptr;
    if (!ev_un) cudaEventCreateWithFlags(&ev_un, cudaEventDisableTiming);
    cudaEventRecord(ev_un, s_p);
    cudaStreamWaitEvent(0, ev_un, 0);
}